// round 4
// baseline (speedup 1.0000x reference)
#include <cuda_runtime.h>
#include <math.h>
#include <float.h>

// Problem dims
#define NB 128
#define ND 256
#define NS 512
#define NK 50
#define NH 256
#define NROWS (NB*NS)            // 65536 (b,s) rows
#define OUT_PRED 0
#define OUT_SCAL0 256
#define OUT_SIM 257
#define OUT_FAR 258
#define OUT_NN 259               // B*S*K floats
#define OUT_AE (259 + NROWS*NK)

typedef unsigned long long ull;

// ---------------- packed f32x2 helpers (FFMA2) ----------------
__device__ __forceinline__ ull pack_dup(float a) {
    ull r; asm("mov.b64 %0, {%1, %1};" : "=l"(r) : "f"(a)); return r;
}
__device__ __forceinline__ void ffma2(ull &c, ull a, ull b) {
    asm("fma.rn.f32x2 %0, %1, %2, %0;" : "+l"(c) : "l"(a), "l"(b));
}
__device__ __forceinline__ float2 unpack2(ull v) {
    float2 f; asm("mov.b64 {%0, %1}, %2;" : "=f"(f.x), "=f"(f.y) : "l"(v)); return f;
}

// ---------------- device scratch ----------------
__device__ __align__(16) float g_tvn[ND*NK];
__device__ __align__(16) float g_tvnp[ND*64];     // padded [D][64]
__device__ __align__(16) float g_invnorm[NROWS];
__device__ __align__(16) float g_tpnT[NK*NROWS];  // [K][B*S]
__device__ __align__(16) float g_cand[NK*64*32];
__device__ __align__(16) float g_mean[NB*ND];
__device__ float g_ae;
__device__ float g_sim;
__device__ float g_far;

// ---------------- kernel 0: prep ----------------
__global__ void prep_kernel(const float* __restrict__ tv) {
    __shared__ float inv[64];
    __shared__ float red[256];
    int tid = threadIdx.x;
    if (tid < NK) {
        float ss = 0.f;
        for (int d = 0; d < ND; d++) { float v = tv[d*NK + tid]; ss += v*v; }
        inv[tid] = 1.0f / fmaxf(sqrtf(ss), 1e-12f);
    }
    __syncthreads();
    for (int i = tid; i < ND*NK; i += 256) g_tvn[i] = tv[i] * inv[i % NK];
    for (int i = tid; i < NB*ND; i += 256) g_mean[i] = 0.f;
    if (tid == 0) { g_ae = 0.f; g_sim = 0.f; }
    __syncthreads();
    for (int i = tid; i < ND*64; i += 256) {
        int d = i >> 6, k = i & 63;
        g_tvnp[i] = (k < NK) ? g_tvn[d*NK + k] : 0.f;
    }
    float acc = 0.f;
    for (int p = tid; p < NK*NK; p += 256) {
        int i = p / NK, j = p % NK;
        float ds = 0.f;
        for (int d = 0; d < ND; d++) ds += g_tvn[d*NK + i] * g_tvn[d*NK + j];
        acc += ds - ((i == j) ? 1.0f : 0.0f);
    }
    red[tid] = acc; __syncthreads();
    for (int s = 128; s > 0; s >>= 1) { if (tid < s) red[tid] += red[tid+s]; __syncthreads(); }
    if (tid == 0) g_far = red[0] / (float)(NK*NK);
}

// ---------------- kernel 1: topic GEMM 256x64xK256 + fused norm/mask/nn ----------------
// grid 256, 256 threads. micro 8 rows x 8 cols. tx = tid&7 (8 col groups), ty = tid>>3 (32 row groups)
__global__ void __launch_bounds__(256) topic_kernel(const float* __restrict__ f,
                                                    float* __restrict__ out_nn) {
    __shared__ float As[16*256];
    __shared__ float Bs[16*64];
    __shared__ float spart[256*8];
    __shared__ float inv_s[256];
    __shared__ float den_s[256];

    int tid = threadIdx.x;
    int tx = tid & 7, ty = tid >> 3;
    int row0 = blockIdx.x * 256;
    int b = row0 >> 9;
    int s00 = row0 & 511;

    ull acc2[8][4];
    #pragma unroll
    for (int i = 0; i < 8; i++)
        #pragma unroll
        for (int j = 0; j < 4; j++) acc2[i][j] = 0ull;
    float ssq[8];
    #pragma unroll
    for (int i = 0; i < 8; i++) ssq[i] = 0.f;

    for (int d0 = 0; d0 < ND; d0 += 16) {
        #pragma unroll
        for (int it = 0; it < 4; it++) {
            int v = tid + it*256;
            int kk = v >> 6, r4 = (v & 63) * 4;
            float4 t4 = *(const float4*)(f + ((size_t)(b*ND + d0 + kk))*NS + s00 + r4);
            *(float4*)&As[kk*256 + r4] = t4;
        }
        {
            int kk = tid >> 4, j4 = (tid & 15) * 4;
            *(float4*)&Bs[kk*64 + j4] = *(const float4*)&g_tvnp[(d0 + kk)*64 + j4];
        }
        __syncthreads();
        #pragma unroll
        for (int kk = 0; kk < 16; kk++) {
            float a[8];
            *(float4*)&a[0] = *(const float4*)&As[kk*256 + ty*8];
            *(float4*)&a[4] = *(const float4*)&As[kk*256 + ty*8 + 4];
            ulonglong2 b01 = *(const ulonglong2*)&Bs[kk*64 + tx*8];
            ulonglong2 b23 = *(const ulonglong2*)&Bs[kk*64 + tx*8 + 4];
            ull bb[4] = {b01.x, b01.y, b23.x, b23.y};
            #pragma unroll
            for (int i = 0; i < 8; i++) {
                ull ad = pack_dup(a[i]);
                #pragma unroll
                for (int j = 0; j < 4; j++) ffma2(acc2[i][j], ad, bb[j]);
            }
            if (tx == 0) {
                #pragma unroll
                for (int i = 0; i < 8; i++) ssq[i] += a[i]*a[i];
            }
        }
        __syncthreads();
    }

    if (tx == 0) {
        #pragma unroll
        for (int i = 0; i < 8; i++) {
            float iv = 1.0f / fmaxf(sqrtf(ssq[i]), 1e-12f);
            inv_s[ty*8 + i] = iv;
            g_invnorm[row0 + ty*8 + i] = iv;
        }
    }
    __syncthreads();

    float tp[8][8], amv[8][8], iv[8];
    #pragma unroll
    for (int i = 0; i < 8; i++) iv[i] = inv_s[ty*8 + i];
    #pragma unroll
    for (int i = 0; i < 8; i++) {
        #pragma unroll
        for (int j = 0; j < 4; j++) {
            float2 c = unpack2(acc2[i][j]);
            tp[i][j*2] = c.x; tp[i][j*2+1] = c.y;
        }
        float psum = 0.f;
        #pragma unroll
        for (int j = 0; j < 8; j++) {
            float t = tp[i][j] * iv[i];
            float am = (t > 0.3f) ? tp[i][j] : 0.f;
            amv[i][j] = am;
            psum += am;                 // pad cols exactly 0
        }
        spart[(ty*8 + i)*8 + tx] = psum;
    }
    __syncthreads();
    {
        float s = 0.f;
        #pragma unroll
        for (int t = 0; t < 8; t++) s += spart[tid*8 + t];
        den_s[tid] = 1.0f / ((s + 0.001f) + 1e-8f);
    }
    __syncthreads();

    #pragma unroll
    for (int i = 0; i < 8; i++) {
        int row = row0 + ty*8 + i;
        float den = den_s[ty*8 + i];
        #pragma unroll
        for (int j = 0; j < 8; j++) {
            int k = tx*8 + j;
            if (k < NK) {
                out_nn[(size_t)row*NK + k] = amv[i][j] * den;
                g_tpnT[(size_t)k*NROWS + row] = tp[i][j] * iv[i];
            }
        }
    }
}

// ---------------- top-k stage 1 ----------------
__global__ void topk1_kernel() {
    int k = blockIdx.y, chunk = blockIdx.x, lane = threadIdx.x;
    const float* src = g_tpnT + (size_t)k*NROWS + chunk*1024;
    float v[32];
    #pragma unroll
    for (int j = 0; j < 32; j++) v[j] = src[j*32 + lane];
    float* dst = g_cand + ((size_t)k*64 + chunk)*32;
    for (int it = 0; it < 32; it++) {
        float lm = -FLT_MAX;
        #pragma unroll
        for (int j = 0; j < 32; j++) lm = fmaxf(lm, v[j]);
        float wm = lm;
        for (int o = 16; o; o >>= 1) wm = fmaxf(wm, __shfl_xor_sync(0xffffffffu, wm, o));
        unsigned msk = __ballot_sync(0xffffffffu, lm == wm);
        int owner = __ffs(msk) - 1;
        if (lane == owner) {
            dst[it] = wm;
            bool rm = false;
            #pragma unroll
            for (int j = 0; j < 32; j++)
                if (!rm && v[j] == wm) { v[j] = -FLT_MAX; rm = true; }
        }
        __syncwarp();
    }
}

// ---------------- top-k stage 2 ----------------
__global__ void topk2_kernel() {
    __shared__ float cd[2048];
    __shared__ float sval[256];
    __shared__ int   sidx[256];
    int tid = threadIdx.x, k = blockIdx.x;
    for (int i = tid; i < 2048; i += 256) cd[i] = g_cand[(size_t)k*2048 + i];
    __syncthreads();
    float total = 0.f;
    for (int it = 0; it < 32; it++) {
        float lm = -FLT_MAX; int li = tid;
        for (int j = tid; j < 2048; j += 256)
            if (cd[j] > lm) { lm = cd[j]; li = j; }
        sval[tid] = lm; sidx[tid] = li;
        __syncthreads();
        for (int s = 128; s > 0; s >>= 1) {
            if (tid < s && sval[tid+s] > sval[tid]) { sval[tid] = sval[tid+s]; sidx[tid] = sidx[tid+s]; }
            __syncthreads();
        }
        if (tid == 0) { total += sval[0]; cd[sidx[0]] = -FLT_MAX; }
        __syncthreads();
    }
    if (tid == 0) atomicAdd(&g_sim, total);
}

// ---------------- fused rec1+rec2 kernel ----------------
// grid 512 (row tiles of 128), 256 threads.
// MMA mapping: tx = tid&31 (32 col groups x 8 = 256), ty = tid>>5 (8 row groups x 16 = 128)
// smem: nn_s[128*52] | rv1t[256*52] | As[16*128] | Bs[16*256]
#define FUS_NN    (128*52)
#define FUS_RV1T  (256*52)
#define FUS_AS    (16*128)
#define FUS_BS    (16*256)
#define FUS_SMEM  ((FUS_NN + FUS_RV1T + FUS_AS + FUS_BS) * 4)
__global__ void __launch_bounds__(256) rec_fused_kernel(const float* __restrict__ f,
                                                        const float* __restrict__ rv1,
                                                        const float* __restrict__ rv2,
                                                        const float* __restrict__ nn_in) {
    extern __shared__ float sm[];
    float* nn_s = sm;
    float* rv1t = sm + FUS_NN;
    float* As   = rv1t + FUS_RV1T;
    float* Bs   = As + FUS_AS;

    int tid = threadIdx.x;
    int tx = tid & 31, ty = tid >> 5;
    int row0 = blockIdx.x * 128;
    int b = row0 >> 9;
    int s00 = row0 & 511;

    // load nn tile [128][50] -> nn_s[128][52]
    const float* src = nn_in + (size_t)row0 * NK;
    for (int idx = tid; idx < 128*NK; idx += 256) {
        int r = idx / NK, k = idx - r*NK;
        nn_s[r*52 + k] = src[idx];
    }
    if (tid < 128) { nn_s[tid*52 + 50] = 0.f; nn_s[tid*52 + 51] = 0.f; }
    // load rv1 transposed: rv1t[h][k] = rv1[k][h]
    for (int idx = tid; idx < NK*NH; idx += 256) {
        int k = idx >> 8, h = idx & 255;
        rv1t[h*52 + k] = rv1[k*NH + h];
    }
    { rv1t[tid*52 + 50] = 0.f; rv1t[tid*52 + 51] = 0.f; }
    __syncthreads();

    ull acc2[16][4];
    #pragma unroll
    for (int i = 0; i < 16; i++)
        #pragma unroll
        for (int j = 0; j < 4; j++) acc2[i][j] = 0ull;

    int rr = tid >> 1;          // 0..127
    int half = tid & 1;         // which 8 of the 16 kk

    for (int k0 = 0; k0 < NH; k0 += 16) {
        // ---- rec1 phase: As[kk][r] = relu(nn[r] . rv1[:, k0+kk]) ----
        {
            ulonglong2 nnv[13];
            const ulonglong2* np = (const ulonglong2*)&nn_s[rr*52];
            #pragma unroll
            for (int q = 0; q < 13; q++) nnv[q] = np[q];
            #pragma unroll
            for (int j = 0; j < 8; j++) {
                int h = k0 + half*8 + j;
                const ulonglong2* rp = (const ulonglong2*)&rv1t[h*52];
                ull z0 = 0ull, z1 = 0ull;
                #pragma unroll
                for (int q = 0; q < 13; q++) {
                    ulonglong2 rv = rp[q];
                    ffma2(z0, nnv[q].x, rv.x);
                    ffma2(z1, nnv[q].y, rv.y);
                }
                float2 c0 = unpack2(z0), c1 = unpack2(z1);
                float val = (c0.x + c0.y) + (c1.x + c1.y);
                As[(half*8 + j)*128 + rr] = fmaxf(val, 0.f);
            }
        }
        // ---- Bs load: rv2 slice [16][256] ----
        #pragma unroll
        for (int it = 0; it < 4; it++) {
            int v = tid + it*256;
            int kk = v >> 6, c4 = (v & 63) * 4;
            *(float4*)&Bs[kk*256 + c4] = *(const float4*)(rv2 + (size_t)(k0 + kk)*ND + c4);
        }
        __syncthreads();
        // ---- MMA: 16 kk, micro 16x8 ----
        #pragma unroll
        for (int kk = 0; kk < 16; kk++) {
            float a[16];
            #pragma unroll
            for (int q = 0; q < 4; q++)
                *(float4*)&a[q*4] = *(const float4*)&As[kk*128 + ty*16 + q*4];
            ulonglong2 b01 = *(const ulonglong2*)&Bs[kk*256 + tx*8];
            ulonglong2 b23 = *(const ulonglong2*)&Bs[kk*256 + tx*8 + 4];
            ull bb[4] = {b01.x, b01.y, b23.x, b23.y};
            #pragma unroll
            for (int i = 0; i < 16; i++) {
                ull ad = pack_dup(a[i]);
                #pragma unroll
                for (int j = 0; j < 4; j++) ffma2(acc2[i][j], ad, bb[j]);
            }
        }
        __syncthreads();
    }

    // unpack accumulators
    float acc[16][8];
    #pragma unroll
    for (int i = 0; i < 16; i++)
        #pragma unroll
        for (int j = 0; j < 4; j++) {
            float2 c = unpack2(acc2[i][j]);
            acc[i][j*2] = c.x; acc[i][j*2+1] = c.y;
        }

    // epilogue: ae_loss + per-d (col) sums over s (rows)
    float invn[16];
    #pragma unroll
    for (int i = 0; i < 16; i++) invn[i] = g_invnorm[row0 + ty*16 + i];
    float aeacc = 0.f;
    float cs[8];
    #pragma unroll
    for (int j = 0; j < 8; j++) cs[j] = 0.f;
    #pragma unroll
    for (int j = 0; j < 8; j++) {
        int col = tx*8 + j;
        const float* fp = f + ((size_t)(b*ND + col))*NS + s00 + ty*16;
        #pragma unroll
        for (int i = 0; i < 16; i++) {
            float c = acc[i][j];
            float xn = fp[i] * invn[i];
            float d = xn - c;
            aeacc += d*d;
            cs[j] += c;
        }
    }
    __syncthreads();
    // col sums: scs[col][ty] in As region (2048 floats = 8KB fits)
    float* scs = As;
    #pragma unroll
    for (int j = 0; j < 8; j++) scs[(tx*8 + j)*8 + ty] = cs[j];
    __syncthreads();
    if (tid < 256) {
        float ssum = 0.f;
        #pragma unroll
        for (int t = 0; t < 8; t++) ssum += scs[tid*8 + t];
        atomicAdd(&g_mean[b*ND + tid], ssum);
    }
    // ae reduce in Bs region
    float* red = Bs;
    red[tid] = aeacc;
    __syncthreads();
    for (int s = 128; s > 0; s >>= 1) { if (tid < s) red[tid] += red[tid+s]; __syncthreads(); }
    if (tid == 0) atomicAdd(&g_ae, red[0]);
}

// ---------------- final ----------------
__global__ void final_kernel(const float* __restrict__ Wc, const float* __restrict__ bc,
                             float* __restrict__ out) {
    int tid = threadIdx.x;
    int b = tid >> 1, c = tid & 1;
    float acc = 0.f;
    for (int d = 0; d < ND; d++) acc += g_mean[b*ND + d] * Wc[d*2 + c];
    out[OUT_PRED + b*2 + c] = acc * (1.0f/512.0f) + bc[c];
    if (tid == 0) {
        out[OUT_SCAL0] = 0.0f;
        out[OUT_SIM]   = -g_sim / (float)(NK * (NB/4));
        out[OUT_FAR]   = g_far;
        out[OUT_AE]    = g_ae / (float)((size_t)NROWS * ND);
    }
}

extern "C" void kernel_launch(void* const* d_in, const int* in_sizes, int n_in,
                              void* d_out, int out_size) {
    const float* f   = (const float*)d_in[0];   // [B,D,S]
    const float* tv  = (const float*)d_in[2];   // [D,K]
    const float* rv1 = (const float*)d_in[3];   // [K,H]
    const float* rv2 = (const float*)d_in[4];   // [H,D]
    const float* Wc  = (const float*)d_in[5];   // [D,NCLS]
    const float* bc  = (const float*)d_in[6];   // [NCLS]
    float* out = (float*)d_out;

    cudaFuncSetAttribute(rec_fused_kernel, cudaFuncAttributeMaxDynamicSharedMemorySize, FUS_SMEM);

    prep_kernel<<<1, 256>>>(tv);
    topic_kernel<<<NROWS/256, 256>>>(f, out + OUT_NN);
    rec_fused_kernel<<<NROWS/128, 256, FUS_SMEM>>>(f, rv1, rv2, out + OUT_NN);
    topk1_kernel<<<dim3(64, NK), 32>>>();
    topk2_kernel<<<NK, 256>>>();
    final_kernel<<<1, 256>>>(Wc, bc, out);
}

// round 5
// speedup vs baseline: 1.2284x; 1.2284x over previous
#include <cuda_runtime.h>
#include <math.h>
#include <float.h>

// Problem dims
#define NB 128
#define ND 256
#define NS 512
#define NK 50
#define NH 256
#define NROWS (NB*NS)            // 65536 (b,s) rows
#define OUT_PRED 0
#define OUT_SCAL0 256
#define OUT_SIM 257
#define OUT_FAR 258
#define OUT_NN 259               // B*S*K floats
#define OUT_AE (259 + NROWS*NK)

typedef unsigned long long ull;

// ---------------- packed f32x2 helpers (FFMA2) ----------------
__device__ __forceinline__ ull pack_dup(float a) {
    ull r; asm("mov.b64 %0, {%1, %1};" : "=l"(r) : "f"(a)); return r;
}
__device__ __forceinline__ void ffma2(ull &c, ull a, ull b) {
    asm("fma.rn.f32x2 %0, %1, %2, %0;" : "+l"(c) : "l"(a), "l"(b));
}
__device__ __forceinline__ float2 unpack2(ull v) {
    float2 f; asm("mov.b64 {%0, %1}, %2;" : "=f"(f.x), "=f"(f.y) : "l"(v)); return f;
}

// ---------------- device scratch ----------------
__device__ __align__(16) float g_tvn[ND*NK];
__device__ __align__(16) float g_tvnp[ND*64];     // padded [D][64]
__device__ __align__(16) float g_invnorm[NROWS];
__device__ __align__(16) float g_tpnT[NK*NROWS];  // [K][B*S]
__device__ __align__(16) float g_nn[NROWS*NK];
__device__ __align__(16) float g_rec1[NROWS*NH];
__device__ __align__(16) float g_mean[NB*ND];
__device__ float g_ae;
__device__ float g_sim;
__device__ float g_far;

// ---------------- kernel 0: prep ----------------
__global__ void prep_kernel(const float* __restrict__ tv) {
    __shared__ float inv[64];
    __shared__ float red[256];
    int tid = threadIdx.x;
    if (tid < NK) {
        float ss = 0.f;
        for (int d = 0; d < ND; d++) { float v = tv[d*NK + tid]; ss += v*v; }
        inv[tid] = 1.0f / fmaxf(sqrtf(ss), 1e-12f);
    }
    __syncthreads();
    for (int i = tid; i < ND*NK; i += 256) g_tvn[i] = tv[i] * inv[i % NK];
    for (int i = tid; i < NB*ND; i += 256) g_mean[i] = 0.f;
    if (tid == 0) { g_ae = 0.f; g_sim = 0.f; }
    __syncthreads();
    for (int i = tid; i < ND*64; i += 256) {
        int d = i >> 6, k = i & 63;
        g_tvnp[i] = (k < NK) ? g_tvn[d*NK + k] : 0.f;
    }
    float acc = 0.f;
    for (int p = tid; p < NK*NK; p += 256) {
        int i = p / NK, j = p % NK;
        float ds = 0.f;
        for (int d = 0; d < ND; d++) ds += g_tvn[d*NK + i] * g_tvn[d*NK + j];
        acc += ds - ((i == j) ? 1.0f : 0.0f);
    }
    red[tid] = acc; __syncthreads();
    for (int s = 128; s > 0; s >>= 1) { if (tid < s) red[tid] += red[tid+s]; __syncthreads(); }
    if (tid == 0) g_far = red[0] / (float)(NK*NK);
}

// ---------------- kernel 1: topic GEMM 256x64xK256 + fused norm/mask/nn ----------------
// 256 threads: tx = tid&7 (8 groups, each owns cols {q*32 + tx*4 + 0..3, q=0,1}),
// ty = tid>>3 (32 row groups of 8)
__global__ void __launch_bounds__(256) topic_kernel(const float* __restrict__ f,
                                                    float* __restrict__ out_nn) {
    __shared__ float As[16*256];
    __shared__ float Bs[16*64];
    __shared__ float spart[256*8];
    __shared__ float inv_s[256];
    __shared__ float den_s[256];

    int tid = threadIdx.x;
    int tx = tid & 7, ty = tid >> 3;
    int row0 = blockIdx.x * 256;
    int b = row0 >> 9;
    int s00 = row0 & 511;

    ull acc2[8][4];
    #pragma unroll
    for (int i = 0; i < 8; i++)
        #pragma unroll
        for (int j = 0; j < 4; j++) acc2[i][j] = 0ull;
    float ssq[8];
    #pragma unroll
    for (int i = 0; i < 8; i++) ssq[i] = 0.f;

    for (int d0 = 0; d0 < ND; d0 += 16) {
        #pragma unroll
        for (int it = 0; it < 4; it++) {
            int v = tid + it*256;
            int kk = v >> 6, r4 = (v & 63) * 4;
            float4 t4 = *(const float4*)(f + ((size_t)(b*ND + d0 + kk))*NS + s00 + r4);
            *(float4*)&As[kk*256 + r4] = t4;
        }
        {
            int kk = tid >> 4, j4 = (tid & 15) * 4;
            *(float4*)&Bs[kk*64 + j4] = *(const float4*)&g_tvnp[(d0 + kk)*64 + j4];
        }
        __syncthreads();
        #pragma unroll
        for (int kk = 0; kk < 16; kk++) {
            float a[8];
            *(float4*)&a[0] = *(const float4*)&As[kk*256 + ty*8];
            *(float4*)&a[4] = *(const float4*)&As[kk*256 + ty*8 + 4];
            // scattered quads: conflict-free (8 distinct 16B granules per warp + broadcast)
            ulonglong2 q0 = *(const ulonglong2*)&Bs[kk*64 + tx*4];
            ulonglong2 q1 = *(const ulonglong2*)&Bs[kk*64 + 32 + tx*4];
            ull bb[4] = {q0.x, q0.y, q1.x, q1.y};
            #pragma unroll
            for (int i = 0; i < 8; i++) {
                ull ad = pack_dup(a[i]);
                #pragma unroll
                for (int j = 0; j < 4; j++) ffma2(acc2[i][j], ad, bb[j]);
            }
            if (tx == 0) {
                #pragma unroll
                for (int i = 0; i < 8; i++) ssq[i] += a[i]*a[i];
            }
        }
        __syncthreads();
    }

    if (tx == 0) {
        #pragma unroll
        for (int i = 0; i < 8; i++) {
            float iv = 1.0f / fmaxf(sqrtf(ssq[i]), 1e-12f);
            inv_s[ty*8 + i] = iv;
            g_invnorm[row0 + ty*8 + i] = iv;
        }
    }
    __syncthreads();

    // col index for local slot j (0..7): k = (j>=4?32:0) + tx*4 + (j&3)
    float tp[8][8], amv[8][8], iv[8];
    #pragma unroll
    for (int i = 0; i < 8; i++) iv[i] = inv_s[ty*8 + i];
    #pragma unroll
    for (int i = 0; i < 8; i++) {
        #pragma unroll
        for (int j = 0; j < 4; j++) {
            float2 c = unpack2(acc2[i][j]);
            tp[i][j*2] = c.x; tp[i][j*2+1] = c.y;
        }
        float psum = 0.f;
        #pragma unroll
        for (int j = 0; j < 8; j++) {
            float t = tp[i][j] * iv[i];
            float am = (t > 0.3f) ? tp[i][j] : 0.f;
            amv[i][j] = am;
            psum += am;                 // pad cols exactly 0
        }
        spart[(ty*8 + i)*8 + tx] = psum;
    }
    __syncthreads();
    {
        float s = 0.f;
        #pragma unroll
        for (int t = 0; t < 8; t++) s += spart[tid*8 + t];
        den_s[tid] = 1.0f / ((s + 0.001f) + 1e-8f);
    }
    __syncthreads();

    #pragma unroll
    for (int i = 0; i < 8; i++) {
        int row = row0 + ty*8 + i;
        float den = den_s[ty*8 + i];
        #pragma unroll
        for (int j = 0; j < 8; j++) {
            int k = ((j >= 4) ? 32 : 0) + tx*4 + (j & 3);
            if (k < NK) {
                float v = amv[i][j] * den;
                out_nn[(size_t)row*NK + k] = v;
                g_nn[(size_t)row*NK + k] = v;
                g_tpnT[(size_t)k*NROWS + row] = tp[i][j] * iv[i];
            }
        }
    }
}

// ---------------- radix top-32 select per concept ----------------
// grid 50, block 1024. smem: hist[4096]u | sscan[1024]u | buf[16384]f | red[1024]f | ridx[1024]i
#define TSEL_CAP 16384
#define TSEL_SMEM ((4096 + 1024 + TSEL_CAP + 1024 + 1024) * 4)
__global__ void __launch_bounds__(1024) topsel_kernel() {
    extern __shared__ unsigned smu[];
    unsigned* hist  = smu;
    unsigned* sscan = smu + 4096;
    float*    buf   = (float*)(smu + 5120);
    float*    red   = buf + TSEL_CAP;
    int*      ridx  = (int*)(red + 1024);
    __shared__ unsigned s_cnt, s_T, s_cntAbove, s_g;
    __shared__ float s_above;

    int tid = threadIdx.x;
    int k = blockIdx.x;
    const float* src = g_tpnT + (size_t)k * NROWS;

    for (int i = tid; i < 4096; i += 1024) hist[i] = 0u;
    if (tid == 0) s_cnt = 0u;
    __syncthreads();

    // pass 1: 12-bit histogram of order-flipped float bits
    for (int i = tid; i < NROWS; i += 1024) {
        unsigned u = __float_as_uint(src[i]);
        u = (u & 0x80000000u) ? ~u : (u | 0x80000000u);
        atomicAdd(&hist[u >> 20], 1u);
    }
    __syncthreads();

    // suffix scan over 1024 groups of 4 bins
    unsigned gsum = hist[4*tid] + hist[4*tid+1] + hist[4*tid+2] + hist[4*tid+3];
    sscan[tid] = gsum;
    __syncthreads();
    for (int off = 1; off < 1024; off <<= 1) {
        unsigned add = (tid + off < 1024) ? sscan[tid + off] : 0u;
        __syncthreads();
        sscan[tid] += add;
        __syncthreads();
    }
    {
        unsigned Sh = sscan[tid];
        unsigned Sn = (tid < 1023) ? sscan[tid + 1] : 0u;
        if (Sh >= 32u && Sn < 32u) s_g = (unsigned)tid;
    }
    __syncthreads();
    if (tid == 0) {
        int g = (int)s_g;
        unsigned cum = (g < 1023) ? sscan[g + 1] : 0u;
        for (int bb = 4*g + 3; bb >= 4*g; bb--) {
            unsigned h = hist[bb];
            if (cum + h >= 32u) { s_T = (unsigned)bb; s_cntAbove = cum; break; }
            cum += h;
        }
    }
    __syncthreads();
    unsigned T = s_T;

    // pass 2: sum strictly-above bins; gather boundary bin
    float sumAbove = 0.f;
    for (int i = tid; i < NROWS; i += 1024) {
        float v = src[i];
        unsigned u = __float_as_uint(v);
        u = (u & 0x80000000u) ? ~u : (u | 0x80000000u);
        unsigned bn = u >> 20;
        if (bn > T) sumAbove += v;
        else if (bn == T) {
            unsigned p = atomicAdd(&s_cnt, 1u);
            if (p < TSEL_CAP) buf[p] = v;
        }
    }
    red[tid] = sumAbove;
    __syncthreads();
    for (int s = 512; s > 0; s >>= 1) { if (tid < s) red[tid] += red[tid+s]; __syncthreads(); }
    if (tid == 0) s_above = red[0];
    __syncthreads();

    int n = (int)min(s_cnt, (unsigned)TSEL_CAP);
    int need = 32 - (int)s_cntAbove;
    float picked = 0.f;
    for (int it = 0; it < need; it++) {
        float lm = -FLT_MAX; int li = 0;
        for (int j = tid; j < n; j += 1024) { float x = buf[j]; if (x > lm) { lm = x; li = j; } }
        red[tid] = lm; ridx[tid] = li;
        __syncthreads();
        for (int s = 512; s > 0; s >>= 1) {
            if (tid < s && red[tid+s] > red[tid]) { red[tid] = red[tid+s]; ridx[tid] = ridx[tid+s]; }
            __syncthreads();
        }
        if (tid == 0) { picked += red[0]; buf[ridx[0]] = -FLT_MAX; }
        __syncthreads();
    }
    if (tid == 0) atomicAdd(&g_sim, s_above + picked);
}

// ---------------- kernel 2: rec1 GEMM 128x128xK50, relu ----------------
#define REC1_SMEM (2 * NK * 128 * 4)
__global__ void __launch_bounds__(256) rec1_kernel(const float* __restrict__ rv1) {
    extern __shared__ float sm[];
    float* As = sm;            // [k][row] 50*128
    float* Bs = sm + NK*128;   // [k][col] 50*128
    int tid = threadIdx.x;
    int tx = tid & 15, ty = tid >> 4;
    int col0 = blockIdx.x * 128;
    int row0 = blockIdx.y * 128;

    const float* src = g_nn + (size_t)row0 * NK;
    for (int v = tid; v < 3200; v += 256) {
        float2 t = *(const float2*)(src + v*2);
        int idx = v*2;
        int r = idx / NK, k = idx - r*NK;
        As[k*128 + r] = t.x;
        As[(k+1)*128 + r] = t.y;
    }
    for (int v = tid; v < 1600; v += 256) {
        int k = v >> 5, j4 = (v & 31) * 4;
        *(float4*)&Bs[k*128 + j4] = *(const float4*)(rv1 + k*NH + col0 + j4);
    }
    __syncthreads();

    ull acc2[8][4];
    #pragma unroll
    for (int i = 0; i < 8; i++)
        #pragma unroll
        for (int j = 0; j < 4; j++) acc2[i][j] = 0ull;

    #pragma unroll 2
    for (int k = 0; k < NK; k++) {
        float a[8];
        *(float4*)&a[0] = *(const float4*)&As[k*128 + ty*8];
        *(float4*)&a[4] = *(const float4*)&As[k*128 + ty*8 + 4];
        ulonglong2 b01 = *(const ulonglong2*)&Bs[k*128 + tx*8];
        ulonglong2 b23 = *(const ulonglong2*)&Bs[k*128 + tx*8 + 4];
        ull bb[4] = {b01.x, b01.y, b23.x, b23.y};
        #pragma unroll
        for (int i = 0; i < 8; i++) {
            ull ad = pack_dup(a[i]);
            #pragma unroll
            for (int j = 0; j < 4; j++) ffma2(acc2[i][j], ad, bb[j]);
        }
    }

    #pragma unroll
    for (int i = 0; i < 8; i++) {
        int row = row0 + ty*8 + i;
        float o[8];
        #pragma unroll
        for (int j = 0; j < 4; j++) {
            float2 c = unpack2(acc2[i][j]);
            o[j*2]   = fmaxf(c.x, 0.f);
            o[j*2+1] = fmaxf(c.y, 0.f);
        }
        *(float4*)&g_rec1[(size_t)row*NH + col0 + tx*8]     = *(float4*)&o[0];
        *(float4*)&g_rec1[(size_t)row*NH + col0 + tx*8 + 4] = *(float4*)&o[4];
    }
}

// ---------------- kernel 3: rec2 GEMM 128x256xK256, fused ae_loss + col sums ----------------
// grid 512 (row tiles). 256 threads: tx = tid&15 owns cols {q*64 + tx*4 + 0..3, q=0..3},
// ty = tid>>4 owns rows ty*8 + 0..7. micro 8x16, conflict-free B loads.
__global__ void __launch_bounds__(256) rec2_kernel(const float* __restrict__ f,
                                                   const float* __restrict__ rv2) {
    __shared__ float As[16*128];   // [kk][row]
    __shared__ float Bs[16*256];   // [kk][col]
    int tid = threadIdx.x;
    int tx = tid & 15, ty = tid >> 4;
    int row0 = blockIdx.x * 128;
    int b = row0 >> 9;
    int s00 = row0 & 511;

    ull acc2[8][8];
    #pragma unroll
    for (int i = 0; i < 8; i++)
        #pragma unroll
        for (int j = 0; j < 8; j++) acc2[i][j] = 0ull;

    for (int k0 = 0; k0 < NH; k0 += 16) {
        {
            int r = tid >> 1, half = tid & 1;
            const float* gp = g_rec1 + (size_t)(row0 + r)*NH + k0 + half*8;
            float4 t0 = *(const float4*)gp;
            float4 t1 = *(const float4*)(gp + 4);
            int kb = half*8;
            As[(kb+0)*128 + r] = t0.x; As[(kb+1)*128 + r] = t0.y;
            As[(kb+2)*128 + r] = t0.z; As[(kb+3)*128 + r] = t0.w;
            As[(kb+4)*128 + r] = t1.x; As[(kb+5)*128 + r] = t1.y;
            As[(kb+6)*128 + r] = t1.z; As[(kb+7)*128 + r] = t1.w;
        }
        #pragma unroll
        for (int it = 0; it < 4; it++) {
            int v = tid + it*256;
            int kk = v >> 6, c4 = (v & 63) * 4;
            *(float4*)&Bs[kk*256 + c4] = *(const float4*)(rv2 + (size_t)(k0 + kk)*ND + c4);
        }
        __syncthreads();
        #pragma unroll
        for (int kk = 0; kk < 16; kk++) {
            float a[8];
            *(float4*)&a[0] = *(const float4*)&As[kk*128 + ty*8];
            *(float4*)&a[4] = *(const float4*)&As[kk*128 + ty*8 + 4];
            ull bb[8];
            #pragma unroll
            for (int q = 0; q < 4; q++) {
                ulonglong2 bp = *(const ulonglong2*)&Bs[kk*256 + q*64 + tx*4];
                bb[q*2] = bp.x; bb[q*2+1] = bp.y;
            }
            #pragma unroll
            for (int i = 0; i < 8; i++) {
                ull ad = pack_dup(a[i]);
                #pragma unroll
                for (int j = 0; j < 8; j++) ffma2(acc2[i][j], ad, bb[j]);
            }
        }
        __syncthreads();
    }

    // epilogue: ae_loss + per-col sums; col for ull slot jj: q=jj>>1, c0 = q*64 + tx*4 + (jj&1)*2
    float invn[8];
    #pragma unroll
    for (int i = 0; i < 8; i++) invn[i] = g_invnorm[row0 + ty*8 + i];
    float aeacc = 0.f;
    float* scs = Bs;   // 256 cols x 16 ty = 4096 floats, Bs free after last sync
    #pragma unroll
    for (int jj = 0; jj < 8; jj++) {
        int q = jj >> 1;
        int c0 = q*64 + tx*4 + (jj & 1)*2;
        float cs0 = 0.f, cs1 = 0.f;
        const float* fp0 = f + ((size_t)(b*ND + c0))*NS + s00 + ty*8;
        const float* fp1 = fp0 + NS;
        #pragma unroll
        for (int i = 0; i < 8; i++) {
            float2 c = unpack2(acc2[i][jj]);
            float d0 = fp0[i] * invn[i] - c.x;
            float d1 = fp1[i] * invn[i] - c.y;
            aeacc += d0*d0 + d1*d1;
            cs0 += c.x; cs1 += c.y;
        }
        scs[c0*16 + ty]     = cs0;
        scs[(c0+1)*16 + ty] = cs1;
    }
    __syncthreads();
    {
        float ssum = 0.f;
        #pragma unroll
        for (int t = 0; t < 16; t++) ssum += scs[tid*16 + t];
        atomicAdd(&g_mean[b*ND + tid], ssum);
    }
    float* red = As;
    red[tid] = aeacc;
    __syncthreads();
    for (int s = 128; s > 0; s >>= 1) { if (tid < s) red[tid] += red[tid+s]; __syncthreads(); }
    if (tid == 0) atomicAdd(&g_ae, red[0]);
}

// ---------------- final ----------------
__global__ void final_kernel(const float* __restrict__ Wc, const float* __restrict__ bc,
                             float* __restrict__ out) {
    int tid = threadIdx.x;
    int b = tid >> 1, c = tid & 1;
    float acc = 0.f;
    for (int d = 0; d < ND; d++) acc += g_mean[b*ND + d] * Wc[d*2 + c];
    out[OUT_PRED + b*2 + c] = acc * (1.0f/512.0f) + bc[c];
    if (tid == 0) {
        out[OUT_SCAL0] = 0.0f;
        out[OUT_SIM]   = -g_sim / (float)(NK * (NB/4));
        out[OUT_FAR]   = g_far;
        out[OUT_AE]    = g_ae / (float)((size_t)NROWS * ND);
    }
}

extern "C" void kernel_launch(void* const* d_in, const int* in_sizes, int n_in,
                              void* d_out, int out_size) {
    const float* f   = (const float*)d_in[0];   // [B,D,S]
    const float* tv  = (const float*)d_in[2];   // [D,K]
    const float* rv1 = (const float*)d_in[3];   // [K,H]
    const float* rv2 = (const float*)d_in[4];   // [H,D]
    const float* Wc  = (const float*)d_in[5];   // [D,NCLS]
    const float* bc  = (const float*)d_in[6];   // [NCLS]
    float* out = (float*)d_out;

    cudaFuncSetAttribute(rec1_kernel, cudaFuncAttributeMaxDynamicSharedMemorySize, REC1_SMEM);
    cudaFuncSetAttribute(topsel_kernel, cudaFuncAttributeMaxDynamicSharedMemorySize, TSEL_SMEM);

    prep_kernel<<<1, 256>>>(tv);
    topic_kernel<<<NROWS/256, 256>>>(f, out + OUT_NN);
    topsel_kernel<<<NK, 1024, TSEL_SMEM>>>();
    rec1_kernel<<<dim3(2, 512), 256, REC1_SMEM>>>(rv1);
    rec2_kernel<<<NROWS/128, 256>>>(f, rv2);
    final_kernel<<<1, 256>>>(Wc, bc, out);
}

// round 6
// speedup vs baseline: 1.3547x; 1.1028x over previous
#include <cuda_runtime.h>
#include <math.h>
#include <float.h>

// Problem dims
#define NB 128
#define ND 256
#define NS 512
#define NK 50
#define NH 256
#define NROWS (NB*NS)            // 65536 (b,s) rows
#define OUT_PRED 0
#define OUT_SCAL0 256
#define OUT_SIM 257
#define OUT_FAR 258
#define OUT_NN 259               // B*S*K floats
#define OUT_AE (259 + NROWS*NK)

typedef unsigned long long ull;

// ---------------- packed f32x2 helpers (FFMA2) ----------------
__device__ __forceinline__ ull pack_dup(float a) {
    ull r; asm("mov.b64 %0, {%1, %1};" : "=l"(r) : "f"(a)); return r;
}
__device__ __forceinline__ void ffma2(ull &c, ull a, ull b) {
    asm("fma.rn.f32x2 %0, %1, %2, %0;" : "+l"(c) : "l"(a), "l"(b));
}
__device__ __forceinline__ float2 unpack2(ull v) {
    float2 f; asm("mov.b64 {%0, %1}, %2;" : "=f"(f.x), "=f"(f.y) : "l"(v)); return f;
}

// ---------------- device scratch ----------------
__device__ __align__(16) float g_tvn[ND*NK];
__device__ __align__(16) float g_tvnp[ND*64];     // padded [D][64]
__device__ __align__(16) float g_invnorm[NROWS];
__device__ __align__(16) float g_tpnT[NK*NROWS];  // [K][B*S]
__device__ __align__(16) float g_nnT[NK*NROWS];   // nn transposed [K][B*S]
__device__ __align__(16) float g_rec1[NROWS*NH];
__device__ __align__(16) float g_mean[NB*ND];
__device__ float g_ae;
__device__ float g_sim;
__device__ float g_far;

// ---------------- kernel 0: prep ----------------
__global__ void prep_kernel(const float* __restrict__ tv) {
    __shared__ float inv[64];
    __shared__ float red[256];
    int tid = threadIdx.x;
    if (tid < NK) {
        float ss = 0.f;
        for (int d = 0; d < ND; d++) { float v = tv[d*NK + tid]; ss += v*v; }
        inv[tid] = 1.0f / fmaxf(sqrtf(ss), 1e-12f);
    }
    __syncthreads();
    for (int i = tid; i < ND*NK; i += 256) g_tvn[i] = tv[i] * inv[i % NK];
    for (int i = tid; i < NB*ND; i += 256) g_mean[i] = 0.f;
    if (tid == 0) { g_ae = 0.f; g_sim = 0.f; }
    __syncthreads();
    for (int i = tid; i < ND*64; i += 256) {
        int d = i >> 6, k = i & 63;
        g_tvnp[i] = (k < NK) ? g_tvn[d*NK + k] : 0.f;
    }
    float acc = 0.f;
    for (int p = tid; p < NK*NK; p += 256) {
        int i = p / NK, j = p % NK;
        float ds = 0.f;
        for (int d = 0; d < ND; d++) ds += g_tvn[d*NK + i] * g_tvn[d*NK + j];
        acc += ds - ((i == j) ? 1.0f : 0.0f);
    }
    red[tid] = acc; __syncthreads();
    for (int s = 128; s > 0; s >>= 1) { if (tid < s) red[tid] += red[tid+s]; __syncthreads(); }
    if (tid == 0) g_far = red[0] / (float)(NK*NK);
}

// ---------------- kernel 1: topic GEMM 256x64xK256 + fused norm/mask/nn ----------------
// 256 threads: tx = tid&7 (cols {q*32 + tx*4, q=0,1}), ty = tid>>3 (rows ty*8..+7)
__global__ void __launch_bounds__(256) topic_kernel(const float* __restrict__ f,
                                                    float* __restrict__ out_nn) {
    __shared__ float As[16*256];
    __shared__ float Bs[16*64];
    __shared__ float spart[256*8];
    __shared__ float inv_s[256];
    __shared__ float den_s[256];

    int tid = threadIdx.x;
    int tx = tid & 7, ty = tid >> 3;
    int row0 = blockIdx.x * 256;
    int b = row0 >> 9;
    int s00 = row0 & 511;

    ull acc2[8][4];
    #pragma unroll
    for (int i = 0; i < 8; i++)
        #pragma unroll
        for (int j = 0; j < 4; j++) acc2[i][j] = 0ull;
    float ssq[8];
    #pragma unroll
    for (int i = 0; i < 8; i++) ssq[i] = 0.f;

    for (int d0 = 0; d0 < ND; d0 += 16) {
        #pragma unroll
        for (int it = 0; it < 4; it++) {
            int v = tid + it*256;
            int kk = v >> 6, r4 = (v & 63) * 4;
            float4 t4 = *(const float4*)(f + ((size_t)(b*ND + d0 + kk))*NS + s00 + r4);
            *(float4*)&As[kk*256 + r4] = t4;
        }
        {
            int kk = tid >> 4, j4 = (tid & 15) * 4;
            *(float4*)&Bs[kk*64 + j4] = *(const float4*)&g_tvnp[(d0 + kk)*64 + j4];
        }
        __syncthreads();
        // software-pipelined kk loop: prefetch next operands before FFMA2 of current
        float a[8], an[8];
        ull bb[4], bn[4];
        {
            *(float4*)&a[0] = *(const float4*)&As[ty*8];
            *(float4*)&a[4] = *(const float4*)&As[ty*8 + 4];
            ulonglong2 q0 = *(const ulonglong2*)&Bs[tx*4];
            ulonglong2 q1 = *(const ulonglong2*)&Bs[32 + tx*4];
            bb[0]=q0.x; bb[1]=q0.y; bb[2]=q1.x; bb[3]=q1.y;
        }
        #pragma unroll
        for (int kk = 0; kk < 16; kk++) {
            if (kk < 15) {
                *(float4*)&an[0] = *(const float4*)&As[(kk+1)*256 + ty*8];
                *(float4*)&an[4] = *(const float4*)&As[(kk+1)*256 + ty*8 + 4];
                ulonglong2 q0 = *(const ulonglong2*)&Bs[(kk+1)*64 + tx*4];
                ulonglong2 q1 = *(const ulonglong2*)&Bs[(kk+1)*64 + 32 + tx*4];
                bn[0]=q0.x; bn[1]=q0.y; bn[2]=q1.x; bn[3]=q1.y;
            }
            #pragma unroll
            for (int i = 0; i < 8; i++) {
                ull ad = pack_dup(a[i]);
                #pragma unroll
                for (int j = 0; j < 4; j++) ffma2(acc2[i][j], ad, bb[j]);
            }
            if (tx == 0) {
                #pragma unroll
                for (int i = 0; i < 8; i++) ssq[i] += a[i]*a[i];
            }
            if (kk < 15) {
                #pragma unroll
                for (int i = 0; i < 8; i++) a[i] = an[i];
                #pragma unroll
                for (int j = 0; j < 4; j++) bb[j] = bn[j];
            }
        }
        __syncthreads();
    }

    if (tx == 0) {
        #pragma unroll
        for (int i = 0; i < 8; i++) {
            float iv = 1.0f / fmaxf(sqrtf(ssq[i]), 1e-12f);
            inv_s[ty*8 + i] = iv;
            g_invnorm[row0 + ty*8 + i] = iv;
        }
    }
    __syncthreads();

    float tp[8][8], amv[8][8], iv[8];
    #pragma unroll
    for (int i = 0; i < 8; i++) iv[i] = inv_s[ty*8 + i];
    #pragma unroll
    for (int i = 0; i < 8; i++) {
        #pragma unroll
        for (int j = 0; j < 4; j++) {
            float2 c = unpack2(acc2[i][j]);
            tp[i][j*2] = c.x; tp[i][j*2+1] = c.y;
        }
        float psum = 0.f;
        #pragma unroll
        for (int j = 0; j < 8; j++) {
            float t = tp[i][j] * iv[i];
            float am = (t > 0.3f) ? tp[i][j] : 0.f;
            amv[i][j] = am;
            psum += am;                 // pad cols exactly 0
        }
        spart[(ty*8 + i)*8 + tx] = psum;
    }
    __syncthreads();
    {
        float s = 0.f;
        #pragma unroll
        for (int t = 0; t < 8; t++) s += spart[tid*8 + t];
        den_s[tid] = 1.0f / ((s + 0.001f) + 1e-8f);
    }
    __syncthreads();

    #pragma unroll
    for (int i = 0; i < 8; i++) {
        int row = row0 + ty*8 + i;
        float den = den_s[ty*8 + i];
        #pragma unroll
        for (int j = 0; j < 8; j++) {
            int k = ((j >= 4) ? 32 : 0) + tx*4 + (j & 3);
            if (k < NK) {
                float v = amv[i][j] * den;
                out_nn[(size_t)row*NK + k] = v;
                g_nnT[(size_t)k*NROWS + row] = v;
                g_tpnT[(size_t)k*NROWS + row] = tp[i][j] * iv[i];
            }
        }
    }
}

// ---------------- radix top-32 select per concept ----------------
#define TSEL_CAP 16384
#define TSEL_SMEM ((4096 + 1024 + TSEL_CAP + 1024 + 1024) * 4)
__global__ void __launch_bounds__(1024) topsel_kernel() {
    extern __shared__ unsigned smu[];
    unsigned* hist  = smu;
    unsigned* sscan = smu + 4096;
    float*    buf   = (float*)(smu + 5120);
    float*    red   = buf + TSEL_CAP;
    int*      ridx  = (int*)(red + 1024);
    __shared__ unsigned s_cnt, s_T, s_cntAbove, s_g;
    __shared__ float s_above;

    int tid = threadIdx.x;
    int k = blockIdx.x;
    const float* src = g_tpnT + (size_t)k * NROWS;

    for (int i = tid; i < 4096; i += 1024) hist[i] = 0u;
    if (tid == 0) s_cnt = 0u;
    __syncthreads();

    for (int i = tid; i < NROWS; i += 1024) {
        unsigned u = __float_as_uint(src[i]);
        u = (u & 0x80000000u) ? ~u : (u | 0x80000000u);
        atomicAdd(&hist[u >> 20], 1u);
    }
    __syncthreads();

    unsigned gsum = hist[4*tid] + hist[4*tid+1] + hist[4*tid+2] + hist[4*tid+3];
    sscan[tid] = gsum;
    __syncthreads();
    for (int off = 1; off < 1024; off <<= 1) {
        unsigned add = (tid + off < 1024) ? sscan[tid + off] : 0u;
        __syncthreads();
        sscan[tid] += add;
        __syncthreads();
    }
    {
        unsigned Sh = sscan[tid];
        unsigned Sn = (tid < 1023) ? sscan[tid + 1] : 0u;
        if (Sh >= 32u && Sn < 32u) s_g = (unsigned)tid;
    }
    __syncthreads();
    if (tid == 0) {
        int g = (int)s_g;
        unsigned cum = (g < 1023) ? sscan[g + 1] : 0u;
        for (int bb = 4*g + 3; bb >= 4*g; bb--) {
            unsigned h = hist[bb];
            if (cum + h >= 32u) { s_T = (unsigned)bb; s_cntAbove = cum; break; }
            cum += h;
        }
    }
    __syncthreads();
    unsigned T = s_T;

    float sumAbove = 0.f;
    for (int i = tid; i < NROWS; i += 1024) {
        float v = src[i];
        unsigned u = __float_as_uint(v);
        u = (u & 0x80000000u) ? ~u : (u | 0x80000000u);
        unsigned bn = u >> 20;
        if (bn > T) sumAbove += v;
        else if (bn == T) {
            unsigned p = atomicAdd(&s_cnt, 1u);
            if (p < TSEL_CAP) buf[p] = v;
        }
    }
    red[tid] = sumAbove;
    __syncthreads();
    for (int s = 512; s > 0; s >>= 1) { if (tid < s) red[tid] += red[tid+s]; __syncthreads(); }
    if (tid == 0) s_above = red[0];
    __syncthreads();

    int n = (int)min(s_cnt, (unsigned)TSEL_CAP);
    int need = 32 - (int)s_cntAbove;
    float picked = 0.f;
    for (int it = 0; it < need; it++) {
        float lm = -FLT_MAX; int li = 0;
        for (int j = tid; j < n; j += 1024) { float x = buf[j]; if (x > lm) { lm = x; li = j; } }
        red[tid] = lm; ridx[tid] = li;
        __syncthreads();
        for (int s = 512; s > 0; s >>= 1) {
            if (tid < s && red[tid+s] > red[tid]) { red[tid] = red[tid+s]; ridx[tid] = ridx[tid+s]; }
            __syncthreads();
        }
        if (tid == 0) { picked += red[0]; buf[ridx[0]] = -FLT_MAX; }
        __syncthreads();
    }
    if (tid == 0) atomicAdd(&g_sim, s_above + picked);
}

// ---------------- kernel 2: rec1 GEMM 128x128xK50, relu ----------------
// A from g_nnT (coalesced). tx&15 cols {tx*4, 64+tx*4}; ty rows ty*8.
#define REC1_SMEM (2 * NK * 128 * 4)
__global__ void __launch_bounds__(256) rec1_kernel(const float* __restrict__ rv1) {
    extern __shared__ float sm[];
    float* As = sm;            // [k][row] 50*128
    float* Bs = sm + NK*128;   // [k][col] 50*128
    int tid = threadIdx.x;
    int tx = tid & 15, ty = tid >> 4;
    int col0 = blockIdx.x * 128;
    int row0 = blockIdx.y * 128;

    for (int v = tid; v < 1600; v += 256) {
        int k = v >> 5, r4 = (v & 31) * 4;
        *(float4*)&As[k*128 + r4] = *(const float4*)&g_nnT[(size_t)k*NROWS + row0 + r4];
    }
    for (int v = tid; v < 1600; v += 256) {
        int k = v >> 5, j4 = (v & 31) * 4;
        *(float4*)&Bs[k*128 + j4] = *(const float4*)(rv1 + k*NH + col0 + j4);
    }
    __syncthreads();

    ull acc2[8][4];
    #pragma unroll
    for (int i = 0; i < 8; i++)
        #pragma unroll
        for (int j = 0; j < 4; j++) acc2[i][j] = 0ull;

    float a[8], an[8];
    ull bb[4], bn[4];
    {
        *(float4*)&a[0] = *(const float4*)&As[ty*8];
        *(float4*)&a[4] = *(const float4*)&As[ty*8 + 4];
        ulonglong2 q0 = *(const ulonglong2*)&Bs[tx*4];
        ulonglong2 q1 = *(const ulonglong2*)&Bs[64 + tx*4];
        bb[0]=q0.x; bb[1]=q0.y; bb[2]=q1.x; bb[3]=q1.y;
    }
    #pragma unroll 2
    for (int k = 0; k < NK; k++) {
        if (k < NK-1) {
            *(float4*)&an[0] = *(const float4*)&As[(k+1)*128 + ty*8];
            *(float4*)&an[4] = *(const float4*)&As[(k+1)*128 + ty*8 + 4];
            ulonglong2 q0 = *(const ulonglong2*)&Bs[(k+1)*128 + tx*4];
            ulonglong2 q1 = *(const ulonglong2*)&Bs[(k+1)*128 + 64 + tx*4];
            bn[0]=q0.x; bn[1]=q0.y; bn[2]=q1.x; bn[3]=q1.y;
        }
        #pragma unroll
        for (int i = 0; i < 8; i++) {
            ull ad = pack_dup(a[i]);
            #pragma unroll
            for (int j = 0; j < 4; j++) ffma2(acc2[i][j], ad, bb[j]);
        }
        if (k < NK-1) {
            #pragma unroll
            for (int i = 0; i < 8; i++) a[i] = an[i];
            #pragma unroll
            for (int j = 0; j < 4; j++) bb[j] = bn[j];
        }
    }

    // store: cols for slot j: {tx*4, tx*4+1, tx*4+2, tx*4+3} (j=0,1) and +64 (j=2,3)
    #pragma unroll
    for (int i = 0; i < 8; i++) {
        int row = row0 + ty*8 + i;
        float o[8];
        #pragma unroll
        for (int j = 0; j < 4; j++) {
            float2 c = unpack2(acc2[i][j]);
            o[j*2]   = fmaxf(c.x, 0.f);
            o[j*2+1] = fmaxf(c.y, 0.f);
        }
        *(float4*)&g_rec1[(size_t)row*NH + col0 + tx*4]      = *(float4*)&o[0];
        *(float4*)&g_rec1[(size_t)row*NH + col0 + 64 + tx*4] = *(float4*)&o[4];
    }
}

// ---------------- kernel 3: rec2 GEMM 128x128xK256, fused ae_loss + col sums ----------------
// grid (2, 512). tx&15 cols {tx*4, 64+tx*4}; ty rows ty*8. acc 8x8 (32 ull).
__global__ void __launch_bounds__(256) rec2_kernel(const float* __restrict__ f,
                                                   const float* __restrict__ rv2) {
    __shared__ float As[16*128];   // [kk][row]
    __shared__ float Bs[16*128];   // [kk][col]
    int tid = threadIdx.x;
    int tx = tid & 15, ty = tid >> 4;
    int col0 = blockIdx.x * 128;
    int row0 = blockIdx.y * 128;
    int b = row0 >> 9;
    int s00 = row0 & 511;

    ull acc2[8][4];
    #pragma unroll
    for (int i = 0; i < 8; i++)
        #pragma unroll
        for (int j = 0; j < 4; j++) acc2[i][j] = 0ull;

    for (int k0 = 0; k0 < NH; k0 += 16) {
        {
            int r = tid >> 1, half = tid & 1;
            const float* gp = g_rec1 + (size_t)(row0 + r)*NH + k0 + half*8;
            float4 t0 = *(const float4*)gp;
            float4 t1 = *(const float4*)(gp + 4);
            int kb = half*8;
            As[(kb+0)*128 + r] = t0.x; As[(kb+1)*128 + r] = t0.y;
            As[(kb+2)*128 + r] = t0.z; As[(kb+3)*128 + r] = t0.w;
            As[(kb+4)*128 + r] = t1.x; As[(kb+5)*128 + r] = t1.y;
            As[(kb+6)*128 + r] = t1.z; As[(kb+7)*128 + r] = t1.w;
        }
        #pragma unroll
        for (int it = 0; it < 2; it++) {
            int v = tid + it*256;
            int kk = v >> 5, c4 = (v & 31) * 4;
            *(float4*)&Bs[kk*128 + c4] = *(const float4*)(rv2 + (size_t)(k0 + kk)*ND + col0 + c4);
        }
        __syncthreads();
        float a[8], an[8];
        ull bb[4], bn[4];
        {
            *(float4*)&a[0] = *(const float4*)&As[ty*8];
            *(float4*)&a[4] = *(const float4*)&As[ty*8 + 4];
            ulonglong2 q0 = *(const ulonglong2*)&Bs[tx*4];
            ulonglong2 q1 = *(const ulonglong2*)&Bs[64 + tx*4];
            bb[0]=q0.x; bb[1]=q0.y; bb[2]=q1.x; bb[3]=q1.y;
        }
        #pragma unroll
        for (int kk = 0; kk < 16; kk++) {
            if (kk < 15) {
                *(float4*)&an[0] = *(const float4*)&As[(kk+1)*128 + ty*8];
                *(float4*)&an[4] = *(const float4*)&As[(kk+1)*128 + ty*8 + 4];
                ulonglong2 q0 = *(const ulonglong2*)&Bs[(kk+1)*128 + tx*4];
                ulonglong2 q1 = *(const ulonglong2*)&Bs[(kk+1)*128 + 64 + tx*4];
                bn[0]=q0.x; bn[1]=q0.y; bn[2]=q1.x; bn[3]=q1.y;
            }
            #pragma unroll
            for (int i = 0; i < 8; i++) {
                ull ad = pack_dup(a[i]);
                #pragma unroll
                for (int j = 0; j < 4; j++) ffma2(acc2[i][j], ad, bb[j]);
            }
            if (kk < 15) {
                #pragma unroll
                for (int i = 0; i < 8; i++) a[i] = an[i];
                #pragma unroll
                for (int j = 0; j < 4; j++) bb[j] = bn[j];
            }
        }
        __syncthreads();
    }

    // epilogue: slot j -> col pair c0 = col0 + ((j>=2)?64:0) + tx*4 + (j&1)*2
    float invn[8];
    #pragma unroll
    for (int i = 0; i < 8; i++) invn[i] = g_invnorm[row0 + ty*8 + i];
    float aeacc = 0.f;
    float* scs = Bs;   // 128 cols x 16 ty = 2048 floats
    #pragma unroll
    for (int jj = 0; jj < 4; jj++) {
        int cl = ((jj >= 2) ? 64 : 0) + tx*4 + (jj & 1)*2;
        int c0 = col0 + cl;
        float cs0 = 0.f, cs1 = 0.f;
        const float* fp0 = f + ((size_t)(b*ND + c0))*NS + s00 + ty*8;
        const float* fp1 = fp0 + NS;
        #pragma unroll
        for (int i = 0; i < 8; i++) {
            float2 c = unpack2(acc2[i][jj]);
            float d0 = fp0[i] * invn[i] - c.x;
            float d1 = fp1[i] * invn[i] - c.y;
            aeacc += d0*d0 + d1*d1;
            cs0 += c.x; cs1 += c.y;
        }
        scs[cl*16 + ty]     = cs0;
        scs[(cl+1)*16 + ty] = cs1;
    }
    __syncthreads();
    if (tid < 128) {
        float ssum = 0.f;
        #pragma unroll
        for (int t = 0; t < 16; t++) ssum += scs[tid*16 + t];
        atomicAdd(&g_mean[b*ND + col0 + tid], ssum);
    }
    float* red = As;
    red[tid] = aeacc;
    __syncthreads();
    for (int s = 128; s > 0; s >>= 1) { if (tid < s) red[tid] += red[tid+s]; __syncthreads(); }
    if (tid == 0) atomicAdd(&g_ae, red[0]);
}

// ---------------- final ----------------
__global__ void final_kernel(const float* __restrict__ Wc, const float* __restrict__ bc,
                             float* __restrict__ out) {
    int tid = threadIdx.x;
    int b = tid >> 1, c = tid & 1;
    float acc = 0.f;
    for (int d = 0; d < ND; d++) acc += g_mean[b*ND + d] * Wc[d*2 + c];
    out[OUT_PRED + b*2 + c] = acc * (1.0f/512.0f) + bc[c];
    if (tid == 0) {
        out[OUT_SCAL0] = 0.0f;
        out[OUT_SIM]   = -g_sim / (float)(NK * (NB/4));
        out[OUT_FAR]   = g_far;
        out[OUT_AE]    = g_ae / (float)((size_t)NROWS * ND);
    }
}

extern "C" void kernel_launch(void* const* d_in, const int* in_sizes, int n_in,
                              void* d_out, int out_size) {
    const float* f   = (const float*)d_in[0];   // [B,D,S]
    const float* tv  = (const float*)d_in[2];   // [D,K]
    const float* rv1 = (const float*)d_in[3];   // [K,H]
    const float* rv2 = (const float*)d_in[4];   // [H,D]
    const float* Wc  = (const float*)d_in[5];   // [D,NCLS]
    const float* bc  = (const float*)d_in[6];   // [NCLS]
    float* out = (float*)d_out;

    cudaFuncSetAttribute(rec1_kernel, cudaFuncAttributeMaxDynamicSharedMemorySize, REC1_SMEM);
    cudaFuncSetAttribute(topsel_kernel, cudaFuncAttributeMaxDynamicSharedMemorySize, TSEL_SMEM);

    prep_kernel<<<1, 256>>>(tv);
    topic_kernel<<<NROWS/256, 256>>>(f, out + OUT_NN);
    topsel_kernel<<<NK, 1024, TSEL_SMEM>>>();
    rec1_kernel<<<dim3(2, 512), 256, REC1_SMEM>>>(rv1);
    rec2_kernel<<<dim3(2, NROWS/128), 256>>>(f, rv2);
    final_kernel<<<1, 256>>>(Wc, bc, out);
}